// round 12
// baseline (speedup 1.0000x reference)
#include <cuda_runtime.h>
#include <cuda_fp16.h>
#include <cstdint>

#define N_NODES 100000
#define N_EDGES 1600000
#define D 128          // D_IN == D_OUT == 128

#define SCAN_BLK 512
#define NB_SCAN ((N_NODES + SCAN_BLK - 1) / SCAN_BLK)   // 196

// ---- device-global scratch (allocation-free rule) ----
__device__ __half g_supph[(size_t)N_NODES * D];    // 25.6 MB (fp16 support)
__device__ int    g_counts[N_NODES];               // zero at load; re-zeroed by fill
__device__ int    g_rowstart[N_NODES + 1];
__device__ int    g_cur[N_NODES];
__device__ unsigned long long g_status[NB_SCAN];   // lookback flags; re-zeroed by fill
__device__ int2   g_edge[N_EDGES];                 // 12.8 MB packed {col, val bits}

#define FLG_A (1ull << 40)
#define FLG_P (2ull << 40)
#define VAL_MASK 0xFFFFFFFFull

// ---- GEMM tiling ----
#define GR 128
#define KT 32
#define XS_S 36    // 32 + 4 pad  (A fragment banks: 4*gid+tig, bijective)
#define WS_S 136   // 128 + 8 pad (B fragment banks: 8*tig+gid, bijective)
#define XS_ELEMS (GR * XS_S)
#define WS_ELEMS (KT * WS_S)
#define STAGE_ELEMS (XS_ELEMS + WS_ELEMS)
#define GEMM_SMEM_BYTES (2 * STAGE_ELEMS * 4)   // 71680 B

__global__ void gemm_tc_kernel(const float*, const float*, const float*);

// ---- side stream + events + func attribute, once per process ----
struct StreamInit {
    cudaStream_t s2;
    cudaEvent_t ev_fork, ev_join;
    StreamInit() {
        cudaStreamCreateWithFlags(&s2, cudaStreamNonBlocking);
        cudaEventCreateWithFlags(&ev_fork, cudaEventDisableTiming);
        cudaEventCreateWithFlags(&ev_join, cudaEventDisableTiming);
        cudaFuncSetAttribute(gemm_tc_kernel,
                             cudaFuncAttributeMaxDynamicSharedMemorySize,
                             GEMM_SMEM_BYTES);
    }
};
static StreamInit g_si;

// ---------------------------------------------------------------------------
// GEMM (tf32 tensor cores, 2-stage cp.async pipeline): support = x@W+b, fp16.
// Unchanged from R8/R10/R11-measured kernel (32.4 us).
// ---------------------------------------------------------------------------
__device__ __forceinline__ unsigned f2tf32(float f) {
    unsigned u;
    asm("cvt.rna.tf32.f32 %0, %1;" : "=r"(u) : "f"(f));
    return u;
}

__device__ __forceinline__ void mma_tf32(float c[4], const unsigned a[4],
                                         const unsigned bb[2]) {
    asm volatile(
        "mma.sync.aligned.m16n8k8.row.col.f32.tf32.tf32.f32 "
        "{%0,%1,%2,%3}, {%4,%5,%6,%7}, {%8,%9}, {%0,%1,%2,%3};"
        : "+f"(c[0]), "+f"(c[1]), "+f"(c[2]), "+f"(c[3])
        : "r"(a[0]), "r"(a[1]), "r"(a[2]), "r"(a[3]),
          "r"(bb[0]), "r"(bb[1]));
}

__device__ __forceinline__ void cpa16(void* smem_dst, const void* gmem_src,
                                      bool pred) {
    unsigned sa = (unsigned)__cvta_generic_to_shared(smem_dst);
    int sz = pred ? 16 : 0;
    asm volatile("cp.async.cg.shared.global [%0], [%1], 16, %2;"
                 :: "r"(sa), "l"(gmem_src), "r"(sz));
}

__global__ __launch_bounds__(256, 2) void gemm_tc_kernel(
    const float* __restrict__ x, const float* __restrict__ W,
    const float* __restrict__ b) {
    extern __shared__ float smem[];
#define XS(st, r, k) smem[(st) * STAGE_ELEMS + (r) * XS_S + (k)]
#define WS(st, k, c) smem[(st) * STAGE_ELEMS + XS_ELEMS + (k) * WS_S + (c)]

    const int tid  = threadIdx.x;
    const int lane = tid & 31;
    const int warp = tid >> 5;
    const int wr   = warp >> 1;
    const int wc   = warp & 1;
    const int gid  = lane >> 2;
    const int tig  = lane & 3;
    const int row0 = blockIdx.x * GR;

    auto prefetch = [&](int st, int kt) {
#pragma unroll
        for (int j = 0; j < 4; j++) {
            int id = tid + j * 256;
            int r = id >> 3, c16 = id & 7;
            int grow = row0 + r;
            bool ok = grow < N_NODES;
            const float* src = x + (size_t)(ok ? grow : 0) * D + kt + c16 * 4;
            cpa16(&XS(st, r, c16 * 4), src, ok);
        }
#pragma unroll
        for (int j = 0; j < 4; j++) {
            int id = tid + j * 256;
            int k = id >> 5, c16 = id & 31;
            cpa16(&WS(st, k, c16 * 4), W + (size_t)(kt + k) * D + c16 * 4, true);
        }
        asm volatile("cp.async.commit_group;");
    };

    float acc[2][8][4];
#pragma unroll
    for (int mi = 0; mi < 2; mi++)
#pragma unroll
        for (int ni = 0; ni < 8; ni++)
#pragma unroll
            for (int q = 0; q < 4; q++) acc[mi][ni][q] = 0.f;

    prefetch(0, 0);

#pragma unroll
    for (int kti = 0; kti < 4; kti++) {
        if (kti < 3) {
            prefetch((kti + 1) & 1, (kti + 1) * KT);
            asm volatile("cp.async.wait_group 1;" ::: "memory");
        } else {
            asm volatile("cp.async.wait_group 0;" ::: "memory");
        }
        __syncthreads();

        const int st = kti & 1;
#pragma unroll
        for (int ks = 0; ks < 4; ks++) {
            const int kb = ks * 8;
            unsigned a[2][4];
#pragma unroll
            for (int mi = 0; mi < 2; mi++) {
                const int r = wr * 32 + mi * 16 + gid;
                a[mi][0] = f2tf32(XS(st, r, kb + tig));
                a[mi][1] = f2tf32(XS(st, r + 8, kb + tig));
                a[mi][2] = f2tf32(XS(st, r, kb + tig + 4));
                a[mi][3] = f2tf32(XS(st, r + 8, kb + tig + 4));
            }
            unsigned bb[8][2];
#pragma unroll
            for (int ni = 0; ni < 8; ni++) {
                const int c = wc * 64 + ni * 8 + gid;
                bb[ni][0] = f2tf32(WS(st, kb + tig, c));
                bb[ni][1] = f2tf32(WS(st, kb + tig + 4, c));
            }
#pragma unroll
            for (int mi = 0; mi < 2; mi++)
#pragma unroll
                for (int ni = 0; ni < 8; ni++)
                    mma_tf32(acc[mi][ni], a[mi], bb[ni]);
        }
        __syncthreads();
    }

#pragma unroll
    for (int mi = 0; mi < 2; mi++) {
#pragma unroll
        for (int ni = 0; ni < 8; ni++) {
            const int col = wc * 64 + ni * 8 + 2 * tig;
            const float b0 = b[col], b1 = b[col + 1];
            const int r0 = row0 + wr * 32 + mi * 16 + gid;
            const int r1 = r0 + 8;
            if (r0 < N_NODES) {
                __half2 h = __floats2half2_rn(acc[mi][ni][0] + b0,
                                              acc[mi][ni][1] + b1);
                *reinterpret_cast<__half2*>(&g_supph[(size_t)r0 * D + col]) = h;
            }
            if (r1 < N_NODES) {
                __half2 h = __floats2half2_rn(acc[mi][ni][2] + b0,
                                              acc[mi][ni][3] + b1);
                *reinterpret_cast<__half2*>(&g_supph[(size_t)r1 * D + col]) = h;
            }
        }
    }
#undef XS
#undef WS
}

// ---------------------------------------------------------------------------
// CSR chain (3 kernels): hist -> lookback scan -> fill(+cleanup)
// hist/fill vectorized: 4 edges per thread via 128-bit loads. (R11-measured)
// ---------------------------------------------------------------------------
__global__ void hist_kernel(const int4* __restrict__ rows4) {
    int i = blockIdx.x * blockDim.x + threadIdx.x;
    if (i < N_EDGES / 4) {
        int4 r = __ldg(&rows4[i]);
        atomicAdd(&g_counts[r.x], 1);
        atomicAdd(&g_counts[r.y], 1);
        atomicAdd(&g_counts[r.z], 1);
        atomicAdd(&g_counts[r.w], 1);
    }
}

__global__ void scan_lookback_kernel() {
    __shared__ int sh[SCAN_BLK];
    __shared__ int s_base;
    const int bkt = blockIdx.x;
    const int tid = threadIdx.x;
    const int g = bkt * SCAN_BLK + tid;
    int v = (g < N_NODES) ? g_counts[g] : 0;
    sh[tid] = v;
    __syncthreads();
#pragma unroll
    for (int d = 1; d < SCAN_BLK; d <<= 1) {
        int t = (tid >= d) ? sh[tid - d] : 0;
        __syncthreads();
        sh[tid] += t;
        __syncthreads();
    }
    const int incl = sh[tid];
    const int total = sh[SCAN_BLK - 1];

    if (tid == 0) {
        if (bkt == 0) {
            atomicExch(&g_status[0], FLG_P | (unsigned long long)total);
            s_base = 0;
        } else {
            atomicExch(&g_status[bkt], FLG_A | (unsigned long long)total);
            long long run = 0;
            int p = bkt - 1;
            while (true) {
                unsigned long long s = atomicAdd(&g_status[p], 0ull);
                if (s & (FLG_A | FLG_P)) {
                    run += (long long)(s & VAL_MASK);
                    if (s & FLG_P) break;
                    p--;
                }
            }
            atomicExch(&g_status[bkt],
                       FLG_P | (unsigned long long)(run + total));
            s_base = (int)run;
        }
    }
    __syncthreads();

    const int base = s_base;
    if (g < N_NODES) {
        int st = base + incl - v;     // exclusive
        g_rowstart[g] = st;
        g_cur[g] = st;
        if (g == N_NODES - 1) g_rowstart[N_NODES] = base + incl;
    }
}

__global__ void fill_kernel(const int4* __restrict__ rows4,
                            const int4* __restrict__ cols4,
                            const float4* __restrict__ vals4) {
    int i = blockIdx.x * blockDim.x + threadIdx.x;
    if (i < N_EDGES / 4) {
        int4 r = __ldg(&rows4[i]);
        int4 c = __ldg(&cols4[i]);
        float4 v = __ldg(&vals4[i]);
        int p0 = atomicAdd(&g_cur[r.x], 1);
        int p1 = atomicAdd(&g_cur[r.y], 1);
        int p2 = atomicAdd(&g_cur[r.z], 1);
        int p3 = atomicAdd(&g_cur[r.w], 1);
        g_edge[p0] = make_int2(c.x, __float_as_int(v.x));
        g_edge[p1] = make_int2(c.y, __float_as_int(v.y));
        g_edge[p2] = make_int2(c.z, __float_as_int(v.z));
        g_edge[p3] = make_int2(c.w, __float_as_int(v.w));
    }
    // cleanup for the next call (grid covers N_EDGES/4 = 400k >= N_NODES)
    if (i < N_NODES) g_counts[i] = 0;
    if (i < NB_SCAN) g_status[i] = 0ull;
}

// ---------------------------------------------------------------------------
// SpMM v4: TWO rows per warp, FOUR-edge unroll per row -> 8 independent
// support gathers in flight per iteration (MLP 8). fp16 gathers (256B/row),
// fp32 accumulate, float4 stores.
// ---------------------------------------------------------------------------
__device__ __forceinline__ void acc_edge(float4& acc, int2 ed, int lane) {
    const float v = __int_as_float(ed.y);
    uint2 h = *reinterpret_cast<const uint2*>(
        &g_supph[(size_t)ed.x * D + lane * 4]);
    float2 a = __half22float2(*reinterpret_cast<__half2*>(&h.x));
    float2 q = __half22float2(*reinterpret_cast<__half2*>(&h.y));
    acc.x += a.x * v; acc.y += a.y * v;
    acc.z += q.x * v; acc.w += q.y * v;
}

__global__ __launch_bounds__(256) void spmm_kernel(float* __restrict__ out) {
    const int wid  = (blockIdx.x * blockDim.x + threadIdx.x) >> 5;
    const int lane = threadIdx.x & 31;
    const int rowA = wid * 2;
    const int rowB = rowA + 1;                 // N_NODES even -> always valid
    if (rowA >= N_NODES) return;

    int sA = __ldg(&g_rowstart[rowA]);
    const int eA = __ldg(&g_rowstart[rowA + 1]);
    int sB = eA;                               // rowstart[rowB] == eA (CSR)
    const int eB = __ldg(&g_rowstart[rowB + 1]);

    float4 accA = make_float4(0.f, 0.f, 0.f, 0.f);
    float4 accB = make_float4(0.f, 0.f, 0.f, 0.f);

    // main loop: 4 edges per row per iter -> 8 independent gathers in flight
    while (sA + 3 < eA && sB + 3 < eB) {
        int2 a0 = __ldg(&g_edge[sA]);
        int2 a1 = __ldg(&g_edge[sA + 1]);
        int2 a2 = __ldg(&g_edge[sA + 2]);
        int2 a3 = __ldg(&g_edge[sA + 3]);
        int2 b0 = __ldg(&g_edge[sB]);
        int2 b1 = __ldg(&g_edge[sB + 1]);
        int2 b2 = __ldg(&g_edge[sB + 2]);
        int2 b3 = __ldg(&g_edge[sB + 3]);
        acc_edge(accA, a0, lane);
        acc_edge(accB, b0, lane);
        acc_edge(accA, a1, lane);
        acc_edge(accB, b1, lane);
        acc_edge(accA, a2, lane);
        acc_edge(accB, b2, lane);
        acc_edge(accA, a3, lane);
        acc_edge(accB, b3, lane);
        sA += 4; sB += 4;
    }
    // drains (2-wide then scalar)
    for (; sA + 1 < eA; sA += 2) {
        int2 a0 = __ldg(&g_edge[sA]);
        int2 a1 = __ldg(&g_edge[sA + 1]);
        acc_edge(accA, a0, lane);
        acc_edge(accA, a1, lane);
    }
    if (sA < eA) acc_edge(accA, __ldg(&g_edge[sA]), lane);
    for (; sB + 1 < eB; sB += 2) {
        int2 b0 = __ldg(&g_edge[sB]);
        int2 b1 = __ldg(&g_edge[sB + 1]);
        acc_edge(accB, b0, lane);
        acc_edge(accB, b1, lane);
    }
    if (sB < eB) acc_edge(accB, __ldg(&g_edge[sB]), lane);

    reinterpret_cast<float4*>(out)[(size_t)rowA * (D / 4) + lane] = accA;
    reinterpret_cast<float4*>(out)[(size_t)rowB * (D / 4) + lane] = accB;
}

// ---------------------------------------------------------------------------
// Launch. Inputs: x, rows, cols, vals, W, b.  Output: f32 [N_NODES, D].
// Fork-join: 3-kernel CSR chain on side stream || pipelined GEMM on capture
// stream; join; SpMM.
// ---------------------------------------------------------------------------
extern "C" void kernel_launch(void* const* d_in, const int* in_sizes, int n_in,
                              void* d_out, int out_size) {
    const float* x    = (const float*)d_in[0];
    const int*   rows = (const int*)d_in[1];
    const int*   cols = (const int*)d_in[2];
    const float* vals = (const float*)d_in[3];
    const float* W    = (const float*)d_in[4];
    const float* b    = (const float*)d_in[5];
    float* out = (float*)d_out;

    cudaEventRecord(g_si.ev_fork, 0);
    cudaStreamWaitEvent(g_si.s2, g_si.ev_fork, 0);

    // --- CSR build chain on side stream (3 kernels, vectorized) ---
    {
        int n4 = N_EDGES / 4;
        hist_kernel<<<(n4 + 255) / 256, 256, 0, g_si.s2>>>((const int4*)rows);
        scan_lookback_kernel<<<NB_SCAN, SCAN_BLK, 0, g_si.s2>>>();
        fill_kernel<<<(n4 + 255) / 256, 256, 0, g_si.s2>>>(
            (const int4*)rows, (const int4*)cols, (const float4*)vals);
    }
    cudaEventRecord(g_si.ev_join, g_si.s2);

    // --- GEMM on the capture stream (overlaps the chain) ---
    gemm_tc_kernel<<<(N_NODES + GR - 1) / GR, 256, GEMM_SMEM_BYTES>>>(x, W, b);

    // --- join, then SpMM (2 rows per warp, MLP 8) ---
    cudaStreamWaitEvent(0, g_si.ev_join, 0);
    {
        long long total_threads = (long long)(N_NODES / 2) * 32;
        int blk = 256;
        int grid = (int)((total_threads + blk - 1) / blk);
        spmm_kernel<<<grid, blk>>>(out);
    }
}

// round 13
// speedup vs baseline: 1.0106x; 1.0106x over previous
#include <cuda_runtime.h>
#include <cuda_fp16.h>
#include <cstdint>

#define N_NODES 100000
#define N_EDGES 1600000
#define D 128          // D_IN == D_OUT == 128

#define SCAN_BLK 512
#define NB_SCAN ((N_NODES + SCAN_BLK - 1) / SCAN_BLK)   // 196

// ---- device-global scratch (allocation-free rule) ----
__device__ __half g_supph[(size_t)N_NODES * D];    // 25.6 MB (fp16 support)
__device__ int    g_counts[N_NODES];               // zero at load; re-zeroed in scan_fill
__device__ int    g_rowstart[N_NODES + 1];
__device__ int    g_cur[N_NODES];
__device__ unsigned long long g_status[NB_SCAN];   // lookback flags; re-zeroed in scan_fill
__device__ int2   g_edge[N_EDGES];                 // 12.8 MB packed {col, val bits}
__device__ int    g_bar_in;                        // grid barrier (returns to 0)
__device__ int    g_bar_out;

#define FLG_A (1ull << 40)
#define FLG_P (2ull << 40)
#define VAL_MASK 0xFFFFFFFFull

// ---- GEMM tiling ----
#define GR 128
#define KT 32
#define XS_S 36    // 32 + 4 pad  (A fragment banks: 4*gid+tig, bijective)
#define WS_S 136   // 128 + 8 pad (B fragment banks: 8*tig+gid, bijective)
#define XS_ELEMS (GR * XS_S)
#define WS_ELEMS (KT * WS_S)
#define STAGE_ELEMS (XS_ELEMS + WS_ELEMS)
#define GEMM_SMEM_BYTES (2 * STAGE_ELEMS * 4)   // 71680 B

__global__ void gemm_tc_kernel(const float*, const float*, const float*);

// ---- side stream + events + func attribute, once per process ----
struct StreamInit {
    cudaStream_t s2;
    cudaEvent_t ev_fork, ev_join;
    StreamInit() {
        cudaStreamCreateWithFlags(&s2, cudaStreamNonBlocking);
        cudaEventCreateWithFlags(&ev_fork, cudaEventDisableTiming);
        cudaEventCreateWithFlags(&ev_join, cudaEventDisableTiming);
        cudaFuncSetAttribute(gemm_tc_kernel,
                             cudaFuncAttributeMaxDynamicSharedMemorySize,
                             GEMM_SMEM_BYTES);
    }
};
static StreamInit g_si;

// ---------------------------------------------------------------------------
// GEMM (tf32 tensor cores, 2-stage cp.async pipeline): support = x@W+b, fp16.
// Unchanged from R8-R12 measured kernel (32.4-32.7 us).
// ---------------------------------------------------------------------------
__device__ __forceinline__ unsigned f2tf32(float f) {
    unsigned u;
    asm("cvt.rna.tf32.f32 %0, %1;" : "=r"(u) : "f"(f));
    return u;
}

__device__ __forceinline__ void mma_tf32(float c[4], const unsigned a[4],
                                         const unsigned bb[2]) {
    asm volatile(
        "mma.sync.aligned.m16n8k8.row.col.f32.tf32.tf32.f32 "
        "{%0,%1,%2,%3}, {%4,%5,%6,%7}, {%8,%9}, {%0,%1,%2,%3};"
        : "+f"(c[0]), "+f"(c[1]), "+f"(c[2]), "+f"(c[3])
        : "r"(a[0]), "r"(a[1]), "r"(a[2]), "r"(a[3]),
          "r"(bb[0]), "r"(bb[1]));
}

__device__ __forceinline__ void cpa16(void* smem_dst, const void* gmem_src,
                                      bool pred) {
    unsigned sa = (unsigned)__cvta_generic_to_shared(smem_dst);
    int sz = pred ? 16 : 0;
    asm volatile("cp.async.cg.shared.global [%0], [%1], 16, %2;"
                 :: "r"(sa), "l"(gmem_src), "r"(sz));
}

__global__ __launch_bounds__(256, 2) void gemm_tc_kernel(
    const float* __restrict__ x, const float* __restrict__ W,
    const float* __restrict__ b) {
    extern __shared__ float smem[];
#define XS(st, r, k) smem[(st) * STAGE_ELEMS + (r) * XS_S + (k)]
#define WS(st, k, c) smem[(st) * STAGE_ELEMS + XS_ELEMS + (k) * WS_S + (c)]

    const int tid  = threadIdx.x;
    const int lane = tid & 31;
    const int warp = tid >> 5;
    const int wr   = warp >> 1;
    const int wc   = warp & 1;
    const int gid  = lane >> 2;
    const int tig  = lane & 3;
    const int row0 = blockIdx.x * GR;

    auto prefetch = [&](int st, int kt) {
#pragma unroll
        for (int j = 0; j < 4; j++) {
            int id = tid + j * 256;
            int r = id >> 3, c16 = id & 7;
            int grow = row0 + r;
            bool ok = grow < N_NODES;
            const float* src = x + (size_t)(ok ? grow : 0) * D + kt + c16 * 4;
            cpa16(&XS(st, r, c16 * 4), src, ok);
        }
#pragma unroll
        for (int j = 0; j < 4; j++) {
            int id = tid + j * 256;
            int k = id >> 5, c16 = id & 31;
            cpa16(&WS(st, k, c16 * 4), W + (size_t)(kt + k) * D + c16 * 4, true);
        }
        asm volatile("cp.async.commit_group;");
    };

    float acc[2][8][4];
#pragma unroll
    for (int mi = 0; mi < 2; mi++)
#pragma unroll
        for (int ni = 0; ni < 8; ni++)
#pragma unroll
            for (int q = 0; q < 4; q++) acc[mi][ni][q] = 0.f;

    prefetch(0, 0);

#pragma unroll
    for (int kti = 0; kti < 4; kti++) {
        if (kti < 3) {
            prefetch((kti + 1) & 1, (kti + 1) * KT);
            asm volatile("cp.async.wait_group 1;" ::: "memory");
        } else {
            asm volatile("cp.async.wait_group 0;" ::: "memory");
        }
        __syncthreads();

        const int st = kti & 1;
#pragma unroll
        for (int ks = 0; ks < 4; ks++) {
            const int kb = ks * 8;
            unsigned a[2][4];
#pragma unroll
            for (int mi = 0; mi < 2; mi++) {
                const int r = wr * 32 + mi * 16 + gid;
                a[mi][0] = f2tf32(XS(st, r, kb + tig));
                a[mi][1] = f2tf32(XS(st, r + 8, kb + tig));
                a[mi][2] = f2tf32(XS(st, r, kb + tig + 4));
                a[mi][3] = f2tf32(XS(st, r + 8, kb + tig + 4));
            }
            unsigned bb[8][2];
#pragma unroll
            for (int ni = 0; ni < 8; ni++) {
                const int c = wc * 64 + ni * 8 + gid;
                bb[ni][0] = f2tf32(WS(st, kb + tig, c));
                bb[ni][1] = f2tf32(WS(st, kb + tig + 4, c));
            }
#pragma unroll
            for (int mi = 0; mi < 2; mi++)
#pragma unroll
                for (int ni = 0; ni < 8; ni++)
                    mma_tf32(acc[mi][ni], a[mi], bb[ni]);
        }
        __syncthreads();
    }

#pragma unroll
    for (int mi = 0; mi < 2; mi++) {
#pragma unroll
        for (int ni = 0; ni < 8; ni++) {
            const int col = wc * 64 + ni * 8 + 2 * tig;
            const float b0 = b[col], b1 = b[col + 1];
            const int r0 = row0 + wr * 32 + mi * 16 + gid;
            const int r1 = r0 + 8;
            if (r0 < N_NODES) {
                __half2 h = __floats2half2_rn(acc[mi][ni][0] + b0,
                                              acc[mi][ni][1] + b1);
                *reinterpret_cast<__half2*>(&g_supph[(size_t)r0 * D + col]) = h;
            }
            if (r1 < N_NODES) {
                __half2 h = __floats2half2_rn(acc[mi][ni][2] + b0,
                                              acc[mi][ni][3] + b1);
                *reinterpret_cast<__half2*>(&g_supph[(size_t)r1 * D + col]) = h;
            }
        }
    }
#undef XS
#undef WS
}

// ---------------------------------------------------------------------------
// CSR chain, 2 kernels: hist -> scan_fill (lookback scan + grid barrier +
// vectorized fill + cleanup, fused). All NB_SCAN=196 blocks are co-resident
// (512 thr, <=4 blocks/SM on 148 SMs), so both the lookback spin and the
// grid barrier are deadlock-free. Barrier counters return to 0 every call.
// ---------------------------------------------------------------------------
__global__ void hist_kernel(const int4* __restrict__ rows4) {
    int i = blockIdx.x * blockDim.x + threadIdx.x;
    if (i < N_EDGES / 4) {
        int4 r = __ldg(&rows4[i]);
        atomicAdd(&g_counts[r.x], 1);
        atomicAdd(&g_counts[r.y], 1);
        atomicAdd(&g_counts[r.z], 1);
        atomicAdd(&g_counts[r.w], 1);
    }
}

__global__ __launch_bounds__(SCAN_BLK) void scan_fill_kernel(
    const int4* __restrict__ rows4, const int4* __restrict__ cols4,
    const float4* __restrict__ vals4) {
    __shared__ int sh[SCAN_BLK];
    __shared__ int s_base;
    const int bkt = blockIdx.x;
    const int tid = threadIdx.x;
    const int g = bkt * SCAN_BLK + tid;

    // ---- phase 1: decoupled-lookback exclusive scan of g_counts ----
    int v = (g < N_NODES) ? g_counts[g] : 0;
    sh[tid] = v;
    __syncthreads();
#pragma unroll
    for (int d = 1; d < SCAN_BLK; d <<= 1) {
        int t = (tid >= d) ? sh[tid - d] : 0;
        __syncthreads();
        sh[tid] += t;
        __syncthreads();
    }
    const int incl = sh[tid];
    const int total = sh[SCAN_BLK - 1];

    if (tid == 0) {
        if (bkt == 0) {
            atomicExch(&g_status[0], FLG_P | (unsigned long long)total);
            s_base = 0;
        } else {
            atomicExch(&g_status[bkt], FLG_A | (unsigned long long)total);
            long long run = 0;
            int p = bkt - 1;
            while (true) {
                unsigned long long s = atomicAdd(&g_status[p], 0ull);
                if (s & (FLG_A | FLG_P)) {
                    run += (long long)(s & VAL_MASK);
                    if (s & FLG_P) break;
                    p--;
                }
            }
            atomicExch(&g_status[bkt],
                       FLG_P | (unsigned long long)(run + total));
            s_base = (int)run;
        }
    }
    __syncthreads();

    const int base = s_base;
    if (g < N_NODES) {
        int st = base + incl - v;     // exclusive
        g_rowstart[g] = st;
        g_cur[g] = st;
        if (g == N_NODES - 1) g_rowstart[N_NODES] = base + incl;
    }

    // ---- grid barrier (arrive) ----
    __threadfence();
    __syncthreads();
    if (tid == 0) {
        atomicAdd(&g_bar_in, 1);
        while (atomicAdd(&g_bar_in, 0) < NB_SCAN) { }
    }
    __syncthreads();

    // ---- phase 2: fill (grid-stride, 4 edges per thread per step) ----
    const int n4 = N_EDGES / 4;
    const int stride = NB_SCAN * SCAN_BLK;     // 100352
    for (int i = bkt * SCAN_BLK + tid; i < n4; i += stride) {
        int4 r = __ldg(&rows4[i]);
        int4 c = __ldg(&cols4[i]);
        float4 vv = __ldg(&vals4[i]);
        int p0 = atomicAdd(&g_cur[r.x], 1);
        int p1 = atomicAdd(&g_cur[r.y], 1);
        int p2 = atomicAdd(&g_cur[r.z], 1);
        int p3 = atomicAdd(&g_cur[r.w], 1);
        g_edge[p0] = make_int2(c.x, __float_as_int(vv.x));
        g_edge[p1] = make_int2(c.y, __float_as_int(vv.y));
        g_edge[p2] = make_int2(c.z, __float_as_int(vv.z));
        g_edge[p3] = make_int2(c.w, __float_as_int(vv.w));
    }

    // ---- cleanup for next call (safe: all blocks passed the lookback) ----
    if (g < N_NODES) g_counts[g] = 0;
    if (tid == 0) g_status[bkt] = 0ull;

    // ---- barrier reset (out-counter; last block zeroes both) ----
    __threadfence();
    __syncthreads();
    if (tid == 0) {
        int done = atomicAdd(&g_bar_out, 1);
        if (done == NB_SCAN - 1) {
            g_bar_in = 0;
            g_bar_out = 0;
            __threadfence();
        }
    }
}

// ---------------------------------------------------------------------------
// SpMM v3 (R11-measured optimum): TWO rows per warp, 2-edge unroll each ->
// 4 independent gathers in flight. fp16 gathers (256B/row), fp32 accumulate,
// float4 stores.
// ---------------------------------------------------------------------------
__device__ __forceinline__ void acc_edge(float4& acc, int2 ed, int lane) {
    const float v = __int_as_float(ed.y);
    uint2 h = *reinterpret_cast<const uint2*>(
        &g_supph[(size_t)ed.x * D + lane * 4]);
    float2 a = __half22float2(*reinterpret_cast<__half2*>(&h.x));
    float2 q = __half22float2(*reinterpret_cast<__half2*>(&h.y));
    acc.x += a.x * v; acc.y += a.y * v;
    acc.z += q.x * v; acc.w += q.y * v;
}

__global__ __launch_bounds__(256) void spmm_kernel(float* __restrict__ out) {
    const int wid  = (blockIdx.x * blockDim.x + threadIdx.x) >> 5;
    const int lane = threadIdx.x & 31;
    const int rowA = wid * 2;
    const int rowB = rowA + 1;                 // N_NODES even -> always valid
    if (rowA >= N_NODES) return;

    int sA = __ldg(&g_rowstart[rowA]);
    const int eA = __ldg(&g_rowstart[rowA + 1]);
    int sB = eA;                               // rowstart[rowB] == eA (CSR)
    const int eB = __ldg(&g_rowstart[rowB + 1]);

    float4 accA = make_float4(0.f, 0.f, 0.f, 0.f);
    float4 accB = make_float4(0.f, 0.f, 0.f, 0.f);

    while (sA + 1 < eA && sB + 1 < eB) {
        int2 a0 = __ldg(&g_edge[sA]);
        int2 a1 = __ldg(&g_edge[sA + 1]);
        int2 b0 = __ldg(&g_edge[sB]);
        int2 b1 = __ldg(&g_edge[sB + 1]);
        acc_edge(accA, a0, lane);
        acc_edge(accB, b0, lane);
        acc_edge(accA, a1, lane);
        acc_edge(accB, b1, lane);
        sA += 2; sB += 2;
    }
    for (; sA + 1 < eA; sA += 2) {
        int2 a0 = __ldg(&g_edge[sA]);
        int2 a1 = __ldg(&g_edge[sA + 1]);
        acc_edge(accA, a0, lane);
        acc_edge(accA, a1, lane);
    }
    if (sA < eA) acc_edge(accA, __ldg(&g_edge[sA]), lane);
    for (; sB + 1 < eB; sB += 2) {
        int2 b0 = __ldg(&g_edge[sB]);
        int2 b1 = __ldg(&g_edge[sB + 1]);
        acc_edge(accB, b0, lane);
        acc_edge(accB, b1, lane);
    }
    if (sB < eB) acc_edge(accB, __ldg(&g_edge[sB]), lane);

    reinterpret_cast<float4*>(out)[(size_t)rowA * (D / 4) + lane] = accA;
    reinterpret_cast<float4*>(out)[(size_t)rowB * (D / 4) + lane] = accB;
}

// ---------------------------------------------------------------------------
// Launch. Inputs: x, rows, cols, vals, W, b.  Output: f32 [N_NODES, D].
// Fork-join: 2-kernel CSR chain on side stream || pipelined GEMM on capture
// stream; join; SpMM.
// ---------------------------------------------------------------------------
extern "C" void kernel_launch(void* const* d_in, const int* in_sizes, int n_in,
                              void* d_out, int out_size) {
    const float* x    = (const float*)d_in[0];
    const int*   rows = (const int*)d_in[1];
    const int*   cols = (const int*)d_in[2];
    const float* vals = (const float*)d_in[3];
    const float* W    = (const float*)d_in[4];
    const float* b    = (const float*)d_in[5];
    float* out = (float*)d_out;

    cudaEventRecord(g_si.ev_fork, 0);
    cudaStreamWaitEvent(g_si.s2, g_si.ev_fork, 0);

    // --- CSR build chain on side stream (2 kernels) ---
    {
        int n4 = N_EDGES / 4;
        hist_kernel<<<(n4 + 255) / 256, 256, 0, g_si.s2>>>((const int4*)rows);
        scan_fill_kernel<<<NB_SCAN, SCAN_BLK, 0, g_si.s2>>>(
            (const int4*)rows, (const int4*)cols, (const float4*)vals);
    }
    cudaEventRecord(g_si.ev_join, g_si.s2);

    // --- GEMM on the capture stream (overlaps the chain) ---
    gemm_tc_kernel<<<(N_NODES + GR - 1) / GR, 256, GEMM_SMEM_BYTES>>>(x, W, b);

    // --- join, then SpMM (2 rows per warp) ---
    cudaStreamWaitEvent(0, g_si.ev_join, 0);
    {
        long long total_threads = (long long)(N_NODES / 2) * 32;
        int blk = 256;
        int grid = (int)((total_threads + blk - 1) / blk);
        spmm_kernel<<<grid, blk>>>(out);
    }
}